// round 3
// baseline (speedup 1.0000x reference)
#include <cuda_runtime.h>
#include <cstdint>
#include <math.h>

#define Bb_ 128
#define Tt_ 512
#define Ii_ 1024
#define Hh_ 1024
#define G4_ 4096
#define Cc_ 512

// Scratch (device globals — allocation-free per harness rules)
__device__ float g_G[(size_t)Tt_ * Bb_ * G4_];   // 1 GiB: x@Wi.T + ctx@Wc.T + bi+bc+bh, [T][B][4H]
__device__ float g_ctxg[Bb_ * G4_];              // ctx@Wc.T + bc + bi + bh
__device__ float g_hd[2][Bb_ * Hh_];             // double-buffered h state
__device__ unsigned g_cnt;                        // grid barrier counter (returns to 0)
__device__ int g_sense;                           // grid barrier sense (even flips -> returns to 0)

__device__ __forceinline__ uint32_t f2tf(float x) {
    uint32_t r;
    asm("cvt.rna.tf32.f32 %0, %1;" : "=r"(r) : "f"(x));
    return r;
}

__device__ __forceinline__ void mma8(float* c, const uint32_t* a, const uint32_t* b) {
    asm("mma.sync.aligned.m16n8k8.row.col.f32.tf32.tf32.f32 "
        "{%0,%1,%2,%3},{%4,%5,%6,%7},{%8,%9},{%0,%1,%2,%3};"
        : "+f"(c[0]), "+f"(c[1]), "+f"(c[2]), "+f"(c[3])
        : "r"(a[0]), "r"(a[1]), "r"(a[2]), "r"(a[3]), "r"(b[0]), "r"(b[1]));
}

// Sense-reversing grid barrier across 128 resident blocks.
__device__ __forceinline__ void gridbar(int& ls) {
    const int target = ls ^ 1;
    __syncthreads();
    if (threadIdx.x == 0) {
        __threadfence();
        if (atomicAdd(&g_cnt, 1u) == 127u) {
            g_cnt = 0u;
            asm volatile("st.release.gpu.s32 [%0], %1;" :: "l"(&g_sense), "r"(target) : "memory");
        } else {
            int v;
            do {
                asm volatile("ld.acquire.gpu.s32 %0, [%1];" : "=r"(v) : "l"(&g_sense) : "memory");
            } while (v != target);
        }
    }
    __syncthreads();
    ls = target;
}

// ---------------------------------------------------------------------------
// Phase 0: ctxg[b][n] = ctx[b]·Wc[n] + bc[n] + bi[n] + bh[n]   (fp32 exact)
// ---------------------------------------------------------------------------
__global__ void __launch_bounds__(256) k_ctxg(const float* __restrict__ ctx,
                                              const float* __restrict__ Wc,
                                              const float* __restrict__ bc,
                                              const float* __restrict__ bi,
                                              const float* __restrict__ bh) {
    __shared__ float cs[8][512];
    const int b0 = blockIdx.y * 8;
    const int n = blockIdx.x * 256 + threadIdx.x;
    for (int i = threadIdx.x; i < 8 * 512; i += 256)
        cs[i >> 9][i & 511] = ctx[(size_t)(b0 + (i >> 9)) * 512 + (i & 511)];
    __syncthreads();

    float acc[8];
#pragma unroll
    for (int r = 0; r < 8; r++) acc[r] = 0.f;

    const float* w = Wc + (size_t)n * 512;
    for (int k4 = 0; k4 < 128; k4++) {
        float4 wv = *(const float4*)(w + (k4 << 2));
#pragma unroll
        for (int r = 0; r < 8; r++) {
            acc[r] += cs[r][k4 * 4 + 0] * wv.x;
            acc[r] += cs[r][k4 * 4 + 1] * wv.y;
            acc[r] += cs[r][k4 * 4 + 2] * wv.z;
            acc[r] += cs[r][k4 * 4 + 3] * wv.w;
        }
    }
    const float bias = bc[n] + bi[n] + bh[n];
#pragma unroll
    for (int r = 0; r < 8; r++)
        g_ctxg[(size_t)(b0 + r) * G4_ + n] = acc[r] + bias;
}

// ---------------------------------------------------------------------------
// Phase 1: G[t][b][n] = x[b][t]·Wi[n] + ctxg[b][n]
// TF32 mma, 128x128 block tile, K-chunk 32, double-buffered swizzled smem.
// grid (32, 512): x = n-tile, y = m-tile (m = b*T + t).
// ---------------------------------------------------------------------------
__global__ void __launch_bounds__(256) k_phase1(const float* __restrict__ x,
                                                const float* __restrict__ Wi) {
    extern __shared__ uint32_t sm1[];
    uint32_t* As = sm1;          // [2][128*32]
    uint32_t* Bs = sm1 + 8192;   // [2][128*32]

    const int tid = threadIdx.x;
    const int lane = tid & 31, warp = tid >> 5;
    const int wm = warp >> 2, wn = warp & 3;
    const int g = lane >> 2, tg = lane & 3;
    const int m0 = blockIdx.y << 7, n0 = blockIdx.x << 7;

    const float* xb = x + (size_t)m0 * 1024;
    const float* wb = Wi + (size_t)n0 * 1024;

    float4 pa[4], pb[4];
    auto LD = [&](int K0) {
#pragma unroll
        for (int j = 0; j < 4; j++) {
            int id = tid + (j << 8);
            int r = id >> 3, c = id & 7;
            pa[j] = *(const float4*)(xb + (size_t)r * 1024 + K0 + (c << 2));
            pb[j] = *(const float4*)(wb + (size_t)r * 1024 + K0 + (c << 2));
        }
    };
    auto ST = [&](int buf) {
#pragma unroll
        for (int j = 0; j < 4; j++) {
            int id = tid + (j << 8);
            int r = id >> 3, c = id & 7;
            int off = (buf << 12) + (r << 5) + ((c << 2) ^ ((r & 7) << 2));
            uint4 va, vb;
            va.x = f2tf(pa[j].x); va.y = f2tf(pa[j].y); va.z = f2tf(pa[j].z); va.w = f2tf(pa[j].w);
            vb.x = f2tf(pb[j].x); vb.y = f2tf(pb[j].y); vb.z = f2tf(pb[j].z); vb.w = f2tf(pb[j].w);
            *(uint4*)(As + off) = va;
            *(uint4*)(Bs + off) = vb;
        }
    };

    float acc[4][4][4];
#pragma unroll
    for (int a = 0; a < 4; a++)
#pragma unroll
        for (int b = 0; b < 4; b++)
#pragma unroll
            for (int c = 0; c < 4; c++) acc[a][b][c] = 0.f;

    LD(0); ST(0); __syncthreads();
    int buf = 0;
    for (int kc = 0; kc < 32; kc++) {
        if (kc < 31) LD((kc + 1) << 5);
        const uint32_t* Ab = As + (buf << 12);
        const uint32_t* Bbp = Bs + (buf << 12);
#pragma unroll
        for (int kk = 0; kk < 4; kk++) {
            const int k0 = kk << 3;
            const int cA0 = (k0 + tg) ^ (g << 2);
            const int cA1 = (k0 + tg + 4) ^ (g << 2);
            uint32_t af[4][4], bf[4][2];
#pragma unroll
            for (int mt = 0; mt < 4; mt++) {
                int r0 = (wm << 6) + (mt << 4) + g;
                af[mt][0] = Ab[(r0 << 5) + cA0];
                af[mt][1] = Ab[((r0 + 8) << 5) + cA0];
                af[mt][2] = Ab[(r0 << 5) + cA1];
                af[mt][3] = Ab[((r0 + 8) << 5) + cA1];
            }
#pragma unroll
            for (int nt = 0; nt < 4; nt++) {
                int rb = (wn << 5) + (nt << 3) + g;
                bf[nt][0] = Bbp[(rb << 5) + cA0];
                bf[nt][1] = Bbp[(rb << 5) + cA1];
            }
#pragma unroll
            for (int mt = 0; mt < 4; mt++)
#pragma unroll
                for (int nt = 0; nt < 4; nt++)
                    mma8(acc[mt][nt], af[mt], bf[nt]);
        }
        if (kc < 31) { buf ^= 1; ST(buf); __syncthreads(); }
    }

    const int b = m0 >> 9;
    const float* crow = g_ctxg + (size_t)b * G4_;
#pragma unroll
    for (int mt = 0; mt < 4; mt++) {
#pragma unroll
        for (int half = 0; half < 2; half++) {
            int m = m0 + (wm << 6) + (mt << 4) + g + half * 8;
            int tt = m & 511;
            float* grow = g_G + ((size_t)tt * Bb_ + b) * G4_;
#pragma unroll
            for (int nt = 0; nt < 4; nt++) {
                int n = n0 + (wn << 5) + (nt << 3) + (tg << 1);
                float2 cg = *(const float2*)(crow + n);
                float2 v;
                v.x = acc[mt][nt][half * 2 + 0] + cg.x;
                v.y = acc[mt][nt][half * 2 + 1] + cg.y;
                *(float2*)(grow + n) = v;
            }
        }
    }
}

// ---------------------------------------------------------------------------
// Phase 2: persistent recurrence. 128 blocks x 256 threads, all resident.
// Block (bm,bj): batch rows [bm*32, +32), h-cols [bj*32, +32), all 4 gates.
// Cell state c lives in registers for the whole 512-step loop.
// ---------------------------------------------------------------------------
__global__ void __launch_bounds__(256) k_rec(const float* __restrict__ h0,
                                             const float* __restrict__ c0,
                                             const float* __restrict__ Wh,
                                             float* __restrict__ out) {
    __shared__ uint32_t As[2][1024];   // 32 x 32 tf32 (swizzled)
    __shared__ uint32_t Bs[2][4096];   // 128 x 32 tf32 (swizzled): 4 gates x 32 j

    const int tid = threadIdx.x, lane = tid & 31, warp = tid >> 5;
    const int wm = warp >> 2, wj = warp & 3;        // 2(M) x 4(J) warps
    const int g = lane >> 2, tg = lane & 3;
    const int bm = blockIdx.x >> 5, bj = blockIdx.x & 31;
    const int b0 = bm << 5, j0 = bj << 5;

    int ls = 0;

    // Prologue: stage h0 into buffer 0 (cooperative, 1 float4/thread)
    {
        int i = blockIdx.x * 1024 + tid * 4;
        *(float4*)&g_hd[0][i] = *(const float4*)(h0 + i);
    }

    // Cell state registers: 4 elements per thread at fixed (row, col)
    const int row_ = b0 + (wm << 4) + g;
    const int col_ = j0 + (wj << 3) + (tg << 1);
    float cst[4];
    cst[0] = c0[row_ * 1024 + col_];
    cst[1] = c0[row_ * 1024 + col_ + 1];
    cst[2] = c0[(row_ + 8) * 1024 + col_];
    cst[3] = c0[(row_ + 8) * 1024 + col_ + 1];

    gridbar(ls);  // barrier #1 (h0 staged)

    // Per-thread load descriptors (constant across steps)
    const int rA = tid >> 3, cA4 = (tid & 7) << 2;
    const int aoff = (rA << 5) + (cA4 ^ ((rA & 7) << 2));
    const float* wptr[4];
    int boff[4];
#pragma unroll
    for (int jj = 0; jj < 4; jj++) {
        int id = tid + (jj << 8);
        int r = id >> 3, c4 = (id & 7) << 2;
        int n = ((r >> 5) << 10) + j0 + (r & 31);   // gate*1024 + j0 + local j
        wptr[jj] = Wh + (size_t)n * 1024 + c4;
        boff[jj] = (r << 5) + (c4 ^ ((r & 7) << 2));
    }

    const size_t OUT_F = (size_t)Bb_ * Tt_ * Hh_;   // offset of h_f block in out

    for (int t = 0; t < Tt_; t++) {
        const float* hb = g_hd[t & 1] + (size_t)(b0 + rA) * 1024 + cA4;

        float acc[4][4];
#pragma unroll
        for (int q = 0; q < 4; q++)
#pragma unroll
            for (int p = 0; p < 4; p++) acc[q][p] = 0.f;

        float4 pa, pb[4];
        pa = *(const float4*)(hb);
#pragma unroll
        for (int jj = 0; jj < 4; jj++) pb[jj] = *(const float4*)(wptr[jj]);
        {
            uint4 va;
            va.x = f2tf(pa.x); va.y = f2tf(pa.y); va.z = f2tf(pa.z); va.w = f2tf(pa.w);
            *(uint4*)&As[0][aoff] = va;
#pragma unroll
            for (int jj = 0; jj < 4; jj++) {
                uint4 vb;
                vb.x = f2tf(pb[jj].x); vb.y = f2tf(pb[jj].y); vb.z = f2tf(pb[jj].z); vb.w = f2tf(pb[jj].w);
                *(uint4*)&Bs[0][boff[jj]] = vb;
            }
        }
        __syncthreads();

        int buf = 0;
        for (int kc = 0; kc < 32; kc++) {
            if (kc < 31) {
                const int K0 = (kc + 1) << 5;
                pa = *(const float4*)(hb + K0);
#pragma unroll
                for (int jj = 0; jj < 4; jj++) pb[jj] = *(const float4*)(wptr[jj] + K0);
            }
            const uint32_t* Ab = As[buf];
            const uint32_t* Bbk = Bs[buf];
#pragma unroll
            for (int kk = 0; kk < 4; kk++) {
                const int k0 = kk << 3;
                const int cc0 = (k0 + tg) ^ (g << 2);
                const int cc1 = (k0 + tg + 4) ^ (g << 2);
                uint32_t af[4];
                const int ra0 = (wm << 4) + g;
                af[0] = Ab[(ra0 << 5) + cc0];
                af[1] = Ab[((ra0 + 8) << 5) + cc0];
                af[2] = Ab[(ra0 << 5) + cc1];
                af[3] = Ab[((ra0 + 8) << 5) + cc1];
#pragma unroll
                for (int q = 0; q < 4; q++) {
                    const int rb = (q << 5) + (wj << 3) + g;
                    uint32_t bf[2];
                    bf[0] = Bbk[(rb << 5) + cc0];
                    bf[1] = Bbk[(rb << 5) + cc1];
                    mma8(acc[q], af, bf);
                }
            }
            if (kc < 31) {
                buf ^= 1;
                uint4 va;
                va.x = f2tf(pa.x); va.y = f2tf(pa.y); va.z = f2tf(pa.z); va.w = f2tf(pa.w);
                *(uint4*)&As[buf][aoff] = va;
#pragma unroll
                for (int jj = 0; jj < 4; jj++) {
                    uint4 vb;
                    vb.x = f2tf(pb[jj].x); vb.y = f2tf(pb[jj].y); vb.z = f2tf(pb[jj].z); vb.w = f2tf(pb[jj].w);
                    *(uint4*)&Bs[buf][boff[jj]] = vb;
                }
                __syncthreads();
            }
        }

        // Epilogue: gates + state update + writes
        const float* Gt = g_G + (size_t)t * (Bb_ * G4_);
        float* hout = g_hd[(t + 1) & 1];
#pragma unroll
        for (int rp = 0; rp < 2; rp++) {
            const int row = row_ + rp * 8;
            const float* Gr = Gt + (size_t)row * G4_ + col_;
            float2 iG = *(const float2*)(Gr);
            float2 fG = *(const float2*)(Gr + 1024);
            float2 gG = *(const float2*)(Gr + 2048);
            float2 oG = *(const float2*)(Gr + 3072);
            float hv[2], cv[2];
#pragma unroll
            for (int e = 0; e < 2; e++) {
                const int p = rp * 2 + e;
                float ig = acc[0][p] + (e ? iG.y : iG.x);
                float fg = acc[1][p] + (e ? fG.y : fG.x);
                float gg = acc[2][p] + (e ? gG.y : gG.x);
                float og = acc[3][p] + (e ? oG.y : oG.x);
                ig = 1.f / (1.f + expf(-ig));
                fg = 1.f / (1.f + expf(-fg));
                gg = tanhf(gg);
                og = 1.f / (1.f + expf(-og));
                float cn = fg * cst[p] + ig * gg;
                cst[p] = cn;
                float hn = og * tanhf(cn);
                hv[e] = hn; cv[e] = cn;
            }
            *(float2*)(hout + (size_t)row * 1024 + col_) = make_float2(hv[0], hv[1]);
            *(float2*)(out + ((size_t)row * Tt_ + t) * Hh_ + col_) = make_float2(hv[0], hv[1]);
            if (t == Tt_ - 1) {
                *(float2*)(out + OUT_F + (size_t)row * Hh_ + col_) = make_float2(hv[0], hv[1]);
                *(float2*)(out + OUT_F + (size_t)Bb_ * Hh_ + (size_t)row * Hh_ + col_) =
                    make_float2(cv[0], cv[1]);
            }
        }

        if (t < Tt_ - 1) gridbar(ls);  // barriers #2..#512 (even total -> sense returns to 0)
    }
}

// ---------------------------------------------------------------------------
extern "C" void kernel_launch(void* const* d_in, const int* in_sizes, int n_in,
                              void* d_out, int out_size) {
    (void)in_sizes; (void)n_in; (void)out_size;
    const float* x   = (const float*)d_in[0];
    const float* h0  = (const float*)d_in[1];
    const float* c0  = (const float*)d_in[2];
    const float* ctx = (const float*)d_in[3];
    const float* Wi  = (const float*)d_in[4];
    const float* bi  = (const float*)d_in[5];
    const float* Wh  = (const float*)d_in[6];
    const float* bh  = (const float*)d_in[7];
    const float* Wc  = (const float*)d_in[8];
    const float* bc  = (const float*)d_in[9];
    float* out = (float*)d_out;

    cudaFuncSetAttribute(k_phase1, cudaFuncAttributeMaxDynamicSharedMemorySize, 65536);

    k_ctxg<<<dim3(16, 16), 256>>>(ctx, Wc, bc, bi, bh);
    k_phase1<<<dim3(32, 512), 256, 65536>>>(x, Wi);
    k_rec<<<128, 256>>>(h0, c0, Wh, out);
}

// round 6
// speedup vs baseline: 1.3030x; 1.3030x over previous
#include <cuda_runtime.h>
#include <cstdint>
#include <math.h>

#define Bb_ 128
#define Tt_ 512
#define Ii_ 1024
#define Hh_ 1024
#define G4_ 4096
#define Cc_ 512

// Scratch (device globals — allocation-free per harness rules)
__device__ float g_G[(size_t)Tt_ * Bb_ * G4_];    // x@Wi.T + ctx@Wc.T + bi+bc+bh, [T][B][4H]
__device__ float g_ctxg[Bb_ * G4_];               // ctx@Wc.T + bc + bi + bh
__device__ float g_hd[2][Bb_ * Hh_];              // double-buffered h state
__device__ uint32_t g_x16[(size_t)Bb_ * Tt_ * (Ii_ / 2)];   // x packed fp16x2 [B*T][512]
__device__ uint32_t g_Wi16[(size_t)G4_ * (Ii_ / 2)];        // Wi packed [4096][512]
__device__ uint32_t g_Wh16[(size_t)G4_ * (Hh_ / 2)];        // Wh packed [4096][512]
__device__ unsigned g_cnt;                         // grid barrier counter (returns to 0)
__device__ int g_sense;                            // grid barrier sense

__device__ __forceinline__ uint32_t pack_h2(float lo, float hi) {
    uint32_t r;
    asm("cvt.rn.f16x2.f32 %0, %1, %2;" : "=r"(r) : "f"(hi), "f"(lo));
    return r;
}

__device__ __forceinline__ void mma16h(float* c, const uint32_t* a, const uint32_t* b) {
    asm("mma.sync.aligned.m16n8k16.row.col.f32.f16.f16.f32 "
        "{%0,%1,%2,%3},{%4,%5,%6,%7},{%8,%9},{%0,%1,%2,%3};"
        : "+f"(c[0]), "+f"(c[1]), "+f"(c[2]), "+f"(c[3])
        : "r"(a[0]), "r"(a[1]), "r"(a[2]), "r"(a[3]), "r"(b[0]), "r"(b[1]));
}

// Sense-reversing grid barrier across 128 resident blocks.
__device__ __forceinline__ void gridbar(int& ls) {
    const int target = ls ^ 1;
    __syncthreads();
    if (threadIdx.x == 0) {
        __threadfence();
        if (atomicAdd(&g_cnt, 1u) == 127u) {
            g_cnt = 0u;
            asm volatile("st.release.gpu.s32 [%0], %1;" :: "l"(&g_sense), "r"(target) : "memory");
        } else {
            int v;
            do {
                asm volatile("ld.acquire.gpu.s32 %0, [%1];" : "=r"(v) : "l"(&g_sense) : "memory");
            } while (v != target);
        }
    }
    __syncthreads();
    ls = target;
}

// ---------------------------------------------------------------------------
// fp32 -> packed fp16x2 conversion. Each thread emits 4 words (8 floats).
// ---------------------------------------------------------------------------
__global__ void __launch_bounds__(256) k_cvt(const float* __restrict__ src,
                                             uint32_t* __restrict__ dst) {
    const size_t i = (size_t)blockIdx.x * 256 + threadIdx.x;
    const float4 a = *(const float4*)(src + i * 8);
    const float4 b = *(const float4*)(src + i * 8 + 4);
    uint4 o;
    o.x = pack_h2(a.x, a.y);
    o.y = pack_h2(a.z, a.w);
    o.z = pack_h2(b.x, b.y);
    o.w = pack_h2(b.z, b.w);
    *(uint4*)(dst + i * 4) = o;
}

// ---------------------------------------------------------------------------
// Phase 0: ctxg[b][n] = ctx[b]·Wc[n] + bc[n] + bi[n] + bh[n]   (fp32 exact)
// ---------------------------------------------------------------------------
__global__ void __launch_bounds__(256) k_ctxg(const float* __restrict__ ctx,
                                              const float* __restrict__ Wc,
                                              const float* __restrict__ bc,
                                              const float* __restrict__ bi,
                                              const float* __restrict__ bh) {
    __shared__ float cs[8][512];
    const int b0 = blockIdx.y * 8;
    const int n = blockIdx.x * 256 + threadIdx.x;
    for (int i = threadIdx.x; i < 8 * 512; i += 256)
        cs[i >> 9][i & 511] = ctx[(size_t)(b0 + (i >> 9)) * 512 + (i & 511)];
    __syncthreads();

    float acc[8];
#pragma unroll
    for (int r = 0; r < 8; r++) acc[r] = 0.f;

    const float* w = Wc + (size_t)n * 512;
    for (int k4 = 0; k4 < 128; k4++) {
        float4 wv = *(const float4*)(w + (k4 << 2));
#pragma unroll
        for (int r = 0; r < 8; r++) {
            acc[r] += cs[r][k4 * 4 + 0] * wv.x;
            acc[r] += cs[r][k4 * 4 + 1] * wv.y;
            acc[r] += cs[r][k4 * 4 + 2] * wv.z;
            acc[r] += cs[r][k4 * 4 + 3] * wv.w;
        }
    }
    const float bias = bc[n] + bi[n] + bh[n];
#pragma unroll
    for (int r = 0; r < 8; r++)
        g_ctxg[(size_t)(b0 + r) * G4_ + n] = acc[r] + bias;
}

// ---------------------------------------------------------------------------
// Phase 1 (fp16 HMMA): G[t][b][n] = x_row·Wi[n] + ctxg[b][n]
// 128x128 block tile, K-chunk 32 (16 packed words), double-buffered smem.
// grid (32, 512): x = n-tile, y = m-tile (m = b*512 + t).
// Smem word layout: [row][16 words], col swizz c^(((r>>1)&3)<<2).
// ---------------------------------------------------------------------------
__global__ void __launch_bounds__(256) k_phase1_h(const uint32_t* __restrict__ x16,
                                                  const uint32_t* __restrict__ Wi16) {
    __shared__ uint32_t As[2][2048];   // 128 x 16
    __shared__ uint32_t Bs[2][2048];

    const int tid = threadIdx.x;
    const int lane = tid & 31, warp = tid >> 5;
    const int wm = warp >> 2, wn = warp & 3;        // 2(M) x 4(N); warp tile 64x32
    const int g = lane >> 2, tg = lane & 3;
    const int m0 = blockIdx.y << 7, n0 = blockIdx.x << 7;

    // loads: thread covers one row-half: r = tid>>1 (128 rows), cb = (tid&1)*8
    const int lr = tid >> 1, cb = (tid & 1) << 3;
    const int lsw = ((lr >> 1) & 3) << 2;
    const int so0 = lr * 16 + (cb ^ lsw);
    const int so1 = lr * 16 + ((cb + 4) ^ lsw);
    const uint32_t* xb = x16 + (size_t)(m0 + lr) * 512 + cb;
    const uint32_t* wb = Wi16 + (size_t)(n0 + lr) * 512 + cb;

    uint4 pa0, pa1, pb0, pb1;
    auto LD = [&](int kc) {
        const int o = kc << 4;
        pa0 = *(const uint4*)(xb + o);
        pa1 = *(const uint4*)(xb + o + 4);
        pb0 = *(const uint4*)(wb + o);
        pb1 = *(const uint4*)(wb + o + 4);
    };
    auto ST = [&](int buf) {
        *(uint4*)&As[buf][so0] = pa0;
        *(uint4*)&As[buf][so1] = pa1;
        *(uint4*)&Bs[buf][so0] = pb0;
        *(uint4*)&Bs[buf][so1] = pb1;
    };

    float acc[4][4][4];
#pragma unroll
    for (int a = 0; a < 4; a++)
#pragma unroll
        for (int b = 0; b < 4; b++)
#pragma unroll
            for (int c = 0; c < 4; c++) acc[a][b][c] = 0.f;

    LD(0); ST(0); __syncthreads();
    int buf = 0;
    for (int kc = 0; kc < 32; kc++) {
        if (kc < 31) LD(kc + 1);
        const uint32_t* Ab = As[buf];
        const uint32_t* Bbp = Bs[buf];
#pragma unroll
        for (int kk = 0; kk < 2; kk++) {
            const int c0 = (kk << 3) + tg;
            const int c1 = c0 + 4;
            uint32_t af[4][4], bf[4][2];
#pragma unroll
            for (int mt = 0; mt < 4; mt++) {
                const int r0 = (wm << 6) + (mt << 4) + g;
                const int s0 = ((r0 >> 1) & 3) << 2;
                const int s1 = (((r0 + 8) >> 1) & 3) << 2;
                af[mt][0] = Ab[r0 * 16 + (c0 ^ s0)];
                af[mt][1] = Ab[(r0 + 8) * 16 + (c0 ^ s1)];
                af[mt][2] = Ab[r0 * 16 + (c1 ^ s0)];
                af[mt][3] = Ab[(r0 + 8) * 16 + (c1 ^ s1)];
            }
#pragma unroll
            for (int nt = 0; nt < 4; nt++) {
                const int rb = (wn << 5) + (nt << 3) + g;
                const int sb_ = ((rb >> 1) & 3) << 2;
                bf[nt][0] = Bbp[rb * 16 + (c0 ^ sb_)];
                bf[nt][1] = Bbp[rb * 16 + (c1 ^ sb_)];
            }
#pragma unroll
            for (int mt = 0; mt < 4; mt++)
#pragma unroll
                for (int nt = 0; nt < 4; nt++)
                    mma16h(acc[mt][nt], af[mt], bf[nt]);
        }
        if (kc < 31) { buf ^= 1; ST(buf); __syncthreads(); }
    }

    // Epilogue: add ctxg, write to G[t][b][n]. Block fits inside one b (128 | 512).
    const int b = m0 >> 9;
    const float* crow = g_ctxg + (size_t)b * G4_;
#pragma unroll
    for (int mt = 0; mt < 4; mt++) {
#pragma unroll
        for (int half = 0; half < 2; half++) {
            int m = m0 + (wm << 6) + (mt << 4) + g + half * 8;
            int tt = m & 511;
            float* grow = g_G + ((size_t)tt * Bb_ + b) * G4_;
#pragma unroll
            for (int nt = 0; nt < 4; nt++) {
                int n = n0 + (wn << 5) + (nt << 3) + (tg << 1);
                float2 cg = *(const float2*)(crow + n);
                float2 v;
                v.x = acc[mt][nt][half * 2 + 0] + cg.x;
                v.y = acc[mt][nt][half * 2 + 1] + cg.y;
                *(float2*)(grow + n) = v;
            }
        }
    }
}

// ---------------------------------------------------------------------------
// Phase 2: persistent recurrence, fp16 HMMA. 128 blocks x 256 threads.
// Block (bm,bj): batch rows [bm*32,+32), h-cols [bj*32,+32), all 4 gates.
// Cell state in registers across all 512 steps.
// ---------------------------------------------------------------------------
__global__ void __launch_bounds__(256) k_rec(const float* __restrict__ h0,
                                             const float* __restrict__ c0,
                                             float* __restrict__ out) {
    __shared__ uint32_t As[2][512];    // 32 x 16 words
    __shared__ uint32_t Bs[2][2048];   // 128 x 16 words (4 gates x 32 j)

    const int tid = threadIdx.x, lane = tid & 31, warp = tid >> 5;
    const int wm = warp >> 2, wj = warp & 3;        // 2(M) x 4(J)
    const int g = lane >> 2, tg = lane & 3;
    const int bm = blockIdx.x >> 5, bj = blockIdx.x & 31;
    const int b0 = bm << 5, j0 = bj << 5;

    int ls = 0;

    // stage h0 into buffer 0
    {
        int i = blockIdx.x * 1024 + tid * 4;
        *(float4*)&g_hd[0][i] = *(const float4*)(h0 + i);
    }

    const int row_ = b0 + (wm << 4) + g;
    const int col_ = j0 + (wj << 3) + (tg << 1);
    float cst[4];
    cst[0] = c0[row_ * 1024 + col_];
    cst[1] = c0[row_ * 1024 + col_ + 1];
    cst[2] = c0[(row_ + 8) * 1024 + col_];
    cst[3] = c0[(row_ + 8) * 1024 + col_ + 1];

    gridbar(ls);  // barrier #1 (h0 staged + Wh16 conversion flushed earlier in stream)

    // A loads: r = tid>>3 (32 rows), f = tid&7 -> floats [4f,4f+4), words c0a = 2f
    const int ar = tid >> 3, af_ = tid & 7;
    const int asw = ((ar >> 1) & 3) << 2;
    const int aoff = ar * 16 + ((af_ << 1) ^ asw);
    // B loads: r = tid>>1 (128 rows), cb = (tid&1)*8
    const int br = tid >> 1, bcb = (tid & 1) << 3;
    const int bsw = ((br >> 1) & 3) << 2;
    const int bo0 = br * 16 + (bcb ^ bsw);
    const int bo1 = br * 16 + ((bcb + 4) ^ bsw);
    const int bn = ((br >> 5) << 10) + j0 + (br & 31);   // gate*1024 + j
    const uint32_t* wrow = g_Wh16 + (size_t)bn * 512 + bcb;

    const size_t OUT_F = (size_t)Bb_ * Tt_ * Hh_;

    for (int t = 0; t < Tt_; t++) {
        const float* hb = g_hd[t & 1] + (size_t)(b0 + ar) * 1024 + (af_ << 2);

        float acc[4][4];
#pragma unroll
        for (int q = 0; q < 4; q++)
#pragma unroll
            for (int p = 0; p < 4; p++) acc[q][p] = 0.f;

        float4 ha;
        uint4 wb0, wb1;
        ha = *(const float4*)(hb);
        wb0 = *(const uint4*)(wrow);
        wb1 = *(const uint4*)(wrow + 4);
        {
            uint2 av;
            av.x = pack_h2(ha.x, ha.y);
            av.y = pack_h2(ha.z, ha.w);
            *(uint2*)&As[0][aoff] = av;
            *(uint4*)&Bs[0][bo0] = wb0;
            *(uint4*)&Bs[0][bo1] = wb1;
        }
        __syncthreads();

        int buf = 0;
        for (int kc = 0; kc < 32; kc++) {
            if (kc < 31) {
                const int o = (kc + 1) << 4;
                ha = *(const float4*)(hb + (o << 1));
                wb0 = *(const uint4*)(wrow + o);
                wb1 = *(const uint4*)(wrow + o + 4);
            }
            const uint32_t* Ab = As[buf];
            const uint32_t* Bbk = Bs[buf];
#pragma unroll
            for (int kk = 0; kk < 2; kk++) {
                const int c0w = (kk << 3) + tg;
                const int c1w = c0w + 4;
                uint32_t afr[4];
                const int ra0 = (wm << 4) + g;
                const int s0 = ((ra0 >> 1) & 3) << 2;
                const int s1 = (((ra0 + 8) >> 1) & 3) << 2;
                afr[0] = Ab[ra0 * 16 + (c0w ^ s0)];
                afr[1] = Ab[(ra0 + 8) * 16 + (c0w ^ s1)];
                afr[2] = Ab[ra0 * 16 + (c1w ^ s0)];
                afr[3] = Ab[(ra0 + 8) * 16 + (c1w ^ s1)];
#pragma unroll
                for (int q = 0; q < 4; q++) {
                    const int rb = (q << 5) + (wj << 3) + g;
                    const int sbq = ((rb >> 1) & 3) << 2;
                    uint32_t bfr[2];
                    bfr[0] = Bbk[rb * 16 + (c0w ^ sbq)];
                    bfr[1] = Bbk[rb * 16 + (c1w ^ sbq)];
                    mma16h(acc[q], afr, bfr);
                }
            }
            if (kc < 31) {
                buf ^= 1;
                uint2 av;
                av.x = pack_h2(ha.x, ha.y);
                av.y = pack_h2(ha.z, ha.w);
                *(uint2*)&As[buf][aoff] = av;
                *(uint4*)&Bs[buf][bo0] = wb0;
                *(uint4*)&Bs[buf][bo1] = wb1;
                __syncthreads();
            }
        }

        // Epilogue: gates + state update + writes
        const float* Gt = g_G + (size_t)t * (Bb_ * G4_);
        float* hout = g_hd[(t + 1) & 1];
#pragma unroll
        for (int rp = 0; rp < 2; rp++) {
            const int row = row_ + rp * 8;
            const float* Gr = Gt + (size_t)row * G4_ + col_;
            float2 iG = *(const float2*)(Gr);
            float2 fG = *(const float2*)(Gr + 1024);
            float2 gG = *(const float2*)(Gr + 2048);
            float2 oG = *(const float2*)(Gr + 3072);
            float hv[2], cv[2];
#pragma unroll
            for (int e = 0; e < 2; e++) {
                const int p = rp * 2 + e;
                float ig = acc[0][p] + (e ? iG.y : iG.x);
                float fg = acc[1][p] + (e ? fG.y : fG.x);
                float gg = acc[2][p] + (e ? gG.y : gG.x);
                float og = acc[3][p] + (e ? oG.y : oG.x);
                ig = 1.f / (1.f + expf(-ig));
                fg = 1.f / (1.f + expf(-fg));
                gg = tanhf(gg);
                og = 1.f / (1.f + expf(-og));
                float cn = fg * cst[p] + ig * gg;
                cst[p] = cn;
                float hn = og * tanhf(cn);
                hv[e] = hn; cv[e] = cn;
            }
            *(float2*)(hout + (size_t)row * 1024 + col_) = make_float2(hv[0], hv[1]);
            *(float2*)(out + ((size_t)row * Tt_ + t) * Hh_ + col_) = make_float2(hv[0], hv[1]);
            if (t == Tt_ - 1) {
                *(float2*)(out + OUT_F + (size_t)row * Hh_ + col_) = make_float2(hv[0], hv[1]);
                *(float2*)(out + OUT_F + (size_t)Bb_ * Hh_ + (size_t)row * Hh_ + col_) =
                    make_float2(cv[0], cv[1]);
            }
        }

        if (t < Tt_ - 1) gridbar(ls);  // total gridbars = 512 (even -> sense returns to 0)
    }
}

// ---------------------------------------------------------------------------
extern "C" void kernel_launch(void* const* d_in, const int* in_sizes, int n_in,
                              void* d_out, int out_size) {
    (void)in_sizes; (void)n_in; (void)out_size;
    const float* x   = (const float*)d_in[0];
    const float* h0  = (const float*)d_in[1];
    const float* c0  = (const float*)d_in[2];
    const float* ctx = (const float*)d_in[3];
    const float* Wi  = (const float*)d_in[4];
    const float* bi  = (const float*)d_in[5];
    const float* Wh  = (const float*)d_in[6];
    const float* bh  = (const float*)d_in[7];
    const float* Wc  = (const float*)d_in[8];
    const float* bc  = (const float*)d_in[9];
    float* out = (float*)d_out;

    uint32_t* x16p;  cudaGetSymbolAddress((void**)&x16p, g_x16);
    uint32_t* wi16p; cudaGetSymbolAddress((void**)&wi16p, g_Wi16);
    uint32_t* wh16p; cudaGetSymbolAddress((void**)&wh16p, g_Wh16);

    k_cvt<<<32768, 256>>>(x, x16p);     // 64M floats -> 32M words
    k_cvt<<<2048, 256>>>(Wi, wi16p);    // 4M floats
    k_cvt<<<2048, 256>>>(Wh, wh16p);    // 4M floats
    k_ctxg<<<dim3(16, 16), 256>>>(ctx, Wc, bc, bi, bh);
    k_phase1_h<<<dim3(32, 512), 256>>>(x16p, wi16p);
    k_rec<<<128, 256>>>(h0, c0, out);
}